// round 16
// baseline (speedup 1.0000x reference)
#include <cuda_runtime.h>
#include <cuda_fp16.h>
#include <cstdint>
#include <math.h>

#define H 16
#define DMODEL 1024
#define DK 64
#define NB 2
#define SEQ 2048
#define MROWS (NB*SEQ)   // 4096
#define BHN (NB*H)       // 32

// ---------------- scratch (device globals; no allocation allowed) ----------
__device__ __half s_xq[MROWS * DMODEL];
__device__ __half s_xk[MROWS * DMODEL];
__device__ __half s_xv[MROWS * DMODEL];
__device__ __half s_c16[MROWS * DMODEL];
__device__ __half s_w[4][DMODEL * DMODEL];
__device__ __half a_q[BHN * SEQ * DK];
__device__ __half a_k[BHN * SEQ * DK];
__device__ __half a_vt[BHN * DK * SEQ];

// ---------------- helpers ---------------------------------------------------
static __device__ __forceinline__ uint32_t smem_u32(const void* p) {
    uint32_t a;
    asm("{ .reg .u64 t; cvta.to.shared.u64 t, %1; cvt.u32.u64 %0, t; }"
        : "=r"(a) : "l"(p));
    return a;
}
static __device__ __forceinline__ void cp16(uint32_t s, const void* g) {
    asm volatile("cp.async.cg.shared.global [%0], [%1], 16;" :: "r"(s), "l"(g));
}
#define CP_COMMIT() asm volatile("cp.async.commit_group;")
template <int N>
static __device__ __forceinline__ void cp_wait() {
    asm volatile("cp.async.wait_group %0;" :: "n"(N));
}
static __device__ __forceinline__ void ldm_x4(uint32_t& r0, uint32_t& r1,
                                              uint32_t& r2, uint32_t& r3, uint32_t a) {
    asm volatile("ldmatrix.sync.aligned.m8n8.x4.shared.b16 {%0,%1,%2,%3}, [%4];"
                 : "=r"(r0), "=r"(r1), "=r"(r2), "=r"(r3) : "r"(a));
}
static __device__ __forceinline__ void mma_f16(float* c, const uint32_t* a,
                                               const uint32_t* b) {
    asm volatile(
        "mma.sync.aligned.m16n8k16.row.col.f32.f16.f16.f32 "
        "{%0,%1,%2,%3}, {%4,%5,%6,%7}, {%8,%9}, {%0,%1,%2,%3};"
        : "+f"(c[0]), "+f"(c[1]), "+f"(c[2]), "+f"(c[3])
        : "r"(a[0]), "r"(a[1]), "r"(a[2]), "r"(a[3]), "r"(b[0]), "r"(b[1]));
}
static __device__ __forceinline__ float ex2(float x) {
    float y; asm("ex2.approx.f32 %0, %1;" : "=f"(y) : "f"(x)); return y;
}
static __device__ __forceinline__ uint32_t pack2h(float a, float b) {
    __half2 h2 = __halves2half2(__float2half_rn(a), __float2half_rn(b));
    return *(uint32_t*)&h2;
}

// ---------------------------------------------------------------------------
// batched convert fp32 -> fp16 ; blockIdx.z selects job
// ---------------------------------------------------------------------------
struct CvtArgs {
    const float* x[4];
    __half* y[4];
};

__global__ void cvt_multi(CvtArgs ja, int n4)
{
    const float* x = ja.x[blockIdx.z];
    uint32_t* y = (uint32_t*)ja.y[blockIdx.z];
    int i = blockIdx.x * 256 + threadIdx.x;
    if (i >= n4) return;
    float4 v = ((const float4*)x)[i];
    y[2 * i] = pack2h(v.x, v.y);
    y[2 * i + 1] = pack2h(v.z, v.w);
}

// ---------------------------------------------------------------------------
// fp16 single-pass GEMM, 512 threads / 16 warps: 256x128 CTA tile,
// 4m x 4n warp grid, warp tile 64x32.  BK=32, stage 24KB (A 16K | B 8K),
// 3-stage cp.async pipeline.  64 acc regs/thread -> no spills; 4 warps/SMSP
// for latency hiding.  Per-output k-order identical to R15 (bitwise same).
// Epilogue modes: 0 fp32 flat | 2 transposed fp16 | 3 head fp16.
// ---------------------------------------------------------------------------
#define NIT2 32      // 1024 / 32
#define GSTG 24576   // 24KB per stage

template <int MODE>
__global__ void __launch_bounds__(512, 1)
gemm_mma(const __half* __restrict__ A, const __half* __restrict__ B,
         const float* __restrict__ bias, float* __restrict__ Y,
         __half* __restrict__ Yh)
{
    extern __shared__ __align__(128) char dsm[];
    const uint32_t sS = smem_u32(dsm);

    const int tid = threadIdx.x;
    const int wid = tid >> 5, lane = tid & 31;
    const int wm = wid >> 2, wn = wid & 3;      // 4m x 4n
    const int m0 = blockIdx.y << 8, n0 = blockIdx.x << 7;

    float acc[4][4][4];
#pragma unroll
    for (int i = 0; i < 4; i++)
#pragma unroll
        for (int j = 0; j < 4; j++)
#pragma unroll
            for (int u = 0; u < 4; u++) acc[i][j][u] = 0.0f;

    const int lc = tid & 3;

    auto load_it = [&](int it2, int st) {
        const int kk = it2 << 5;
        uint32_t b = sS + (uint32_t)st * GSTG;
        // A: 1024 chunks, 2 per thread
#pragma unroll
        for (int j = 0; j < 2; j++) {
            int cid = tid + 512 * j;
            int row = cid >> 2;
            uint32_t off = (uint32_t)(row * 64 + ((lc ^ (row & 3)) << 4));
            size_t ga = (size_t)(m0 + row) * DMODEL + kk + lc * 8;
            cp16(b + off, A + ga);
        }
        // B: 512 chunks, 1 per thread
        {
            int row = tid >> 2;
            uint32_t off = (uint32_t)(row * 64 + ((lc ^ (row & 3)) << 4));
            size_t gb = (size_t)(n0 + row) * DMODEL + kk + lc * 8;
            cp16(b + 16384u + off, B + gb);
        }
        CP_COMMIT();
    };

    const int arow = wm * 64 + (lane & 15);
    const int abit = lane >> 4;
    const int brow = wn * 32 + (lane & 7) + ((lane >> 4) & 1) * 8;
    const int bbit = (lane >> 3) & 1;

    load_it(0, 0);
    load_it(1, 1);

    int st = 0;
    for (int it = 0; it < NIT2; ++it) {
        if (it + 1 < NIT2) cp_wait<1>(); else cp_wait<0>();
        __syncthreads();
        if (it + 2 < NIT2) {
            int st2 = st + 2; if (st2 >= 3) st2 -= 3;
            load_it(it + 2, st2);
        }
        const uint32_t sb = sS + (uint32_t)st * GSTG;
#pragma unroll
        for (int ks = 0; ks < 2; ks++) {
            uint32_t bh4[2][4];
#pragma unroll
            for (int np = 0; np < 2; np++) {
                int row = brow + np * 16;
                int ch = 2 * ks + bbit;
                uint32_t off = (uint32_t)(row * 64 + ((ch ^ (row & 3)) << 4));
                ldm_x4(bh4[np][0], bh4[np][1], bh4[np][2], bh4[np][3], sb + 16384u + off);
            }
            uint32_t af[4][4];
#pragma unroll
            for (int mt = 0; mt < 4; mt++) {
                int row = arow + mt * 16;
                int ch = 2 * ks + abit;
                uint32_t ad = sb + (uint32_t)(row * 64 + ((ch ^ (row & 3)) << 4));
                ldm_x4(af[mt][0], af[mt][1], af[mt][2], af[mt][3], ad);
            }
#pragma unroll
            for (int mt = 0; mt < 4; mt++)
#pragma unroll
                for (int nn = 0; nn < 4; nn++)
                    mma_f16(acc[mt][nn], af[mt], bh4[nn >> 1] + (nn & 1) * 2);
        }
        if (++st == 3) st = 0;
    }

    const int ml = lane >> 2;
    const int nl = (lane & 3) << 1;
#pragma unroll
    for (int mt = 0; mt < 4; mt++) {
#pragma unroll
        for (int half = 0; half < 2; half++) {
            int m = m0 + wm * 64 + mt * 16 + ml + half * 8;
#pragma unroll
            for (int nn = 0; nn < 4; nn++) {
                int n = n0 + wn * 32 + nn * 8 + nl;
                float x = acc[mt][nn][2 * half + 0] + bias[n + 0];
                float y = acc[mt][nn][2 * half + 1] + bias[n + 1];
                if (MODE == 0) {
                    float2 o; o.x = x; o.y = y;
                    *(float2*)&Y[(size_t)m * DMODEL + n] = o;
                } else {
                    int bb = m >> 11, s = m & 2047;
                    int h = n >> 6, d = n & 63;
                    if (MODE == 3) {
                        size_t idx = (size_t)((bb * H + h) * SEQ + s) * DK + d;
                        *(uint32_t*)&Yh[idx] = pack2h(x, y);
                    } else {
                        size_t base = (size_t)((bb * H + h) * DK + d) * SEQ + s;
                        Yh[base] = __float2half_rn(x);
                        Yh[base + SEQ] = __float2half_rn(y);
                    }
                }
            }
        }
    }
}

// ---------------------------------------------------------------------------
// fp16 flash attention (R15-proven): 4 warps x 32 q-rows, 128 thr, 2 CTA/SM.
// BQ=128, BKV=64.  Q frags resident; K/V^T double-buffered.
// Smem: Q 16K | 2 x (K 8K | V 8K) = 48KB.
// ---------------------------------------------------------------------------
__global__ void __launch_bounds__(128, 2)
attn_mma()
{
    extern __shared__ __align__(128) char dsm[];
    const uint32_t sbase = smem_u32(dsm);
    const uint32_t sQ = sbase;
    const uint32_t sKV = sbase + 16384;

    const int bh = blockIdx.x;
    const int q0 = blockIdx.y << 7;
    const int tid = threadIdx.x, wid = tid >> 5, lane = tid & 31;

    const __half* qg = a_q + (size_t)bh * SEQ * DK;
    const __half* kg = a_k + (size_t)bh * SEQ * DK;
    const __half* vg = a_vt + (size_t)bh * DK * SEQ;

#pragma unroll
    for (int j = 0; j < 8; j++) {
        int cid = tid + 128 * j;
        int hr = cid >> 2, c = cid & 3;
        int qrow = hr & 127, panel = hr >> 7;
        uint32_t off = (uint32_t)(hr * 64 + ((c ^ (hr & 3)) << 4));
        const size_t src = (size_t)(q0 + qrow) * DK + panel * 32 + c * 8;
        cp16(sQ + off, qg + src);
    }
    CP_COMMIT();
    cp_wait<0>();
    __syncthreads();

    uint32_t fQ[2][4][4];
#pragma unroll
    for (int mb = 0; mb < 2; mb++) {
        const int row = wid * 32 + mb * 16 + (lane & 15);
#pragma unroll
        for (int kf = 0; kf < 4; kf++) {
            int ch = ((kf & 1) << 1) + (lane >> 4);
            uint32_t off = (uint32_t)((kf >> 1) * 8192 + row * 64 + ((ch ^ (row & 3)) << 4));
            ldm_x4(fQ[mb][kf][0], fQ[mb][kf][1], fQ[mb][kf][2], fQ[mb][kf][3], sQ + off);
        }
    }

    float ctxa[2][8][4];
#pragma unroll
    for (int mb = 0; mb < 2; mb++)
#pragma unroll
        for (int i = 0; i < 8; i++)
#pragma unroll
            for (int u = 0; u < 4; u++) ctxa[mb][i][u] = 0.0f;
    float mrun[2][2], lrun[2][2];
#pragma unroll
    for (int mb = 0; mb < 2; mb++) {
        mrun[mb][0] = -1e30f; mrun[mb][1] = -1e30f;
        lrun[mb][0] = 0.0f;   lrun[mb][1] = 0.0f;
    }

    auto load_kv = [&](int kt, int buf) {
        uint32_t base = sKV + buf * 16384;
#pragma unroll
        for (int j = 0; j < 4; j++) {
            int cid = tid + 128 * j;
            int hr = cid >> 2, c = cid & 3;
            uint32_t off = (uint32_t)(hr * 64 + ((c ^ (hr & 3)) << 4));
            int lo6 = hr & 63, pan = hr >> 6;
            size_t ksrc = (size_t)(kt + lo6) * DK + pan * 32 + c * 8;
            size_t vsrc = (size_t)lo6 * SEQ + kt + pan * 32 + c * 8;
            cp16(base + off, kg + ksrc);
            cp16(base + 8192 + off, vg + vsrc);
        }
        CP_COMMIT();
    };

    const int brow = (lane & 7) + ((lane >> 4) & 1) * 8;
    const int bbit = (lane >> 3) & 1;
    const float C2 = 0.18033688f;   // log2(e)/8

    load_kv(0, 0);

    for (int t = 0; t < SEQ / 64; ++t) {
        if (t + 1 < SEQ / 64) { load_kv((t + 1) * 64, (t + 1) & 1); cp_wait<1>(); }
        else cp_wait<0>();
        __syncthreads();

        const uint32_t base = sKV + (t & 1) * 16384;

        float sacc[2][8][4];
#pragma unroll
        for (int mb = 0; mb < 2; mb++)
#pragma unroll
            for (int i = 0; i < 8; i++)
#pragma unroll
                for (int u = 0; u < 4; u++) sacc[mb][i][u] = 0.0f;

#pragma unroll
        for (int kf = 0; kf < 4; kf++) {
#pragma unroll
            for (int np = 0; np < 4; np++) {
                int row = np * 16 + brow;
                int ch = ((kf & 1) << 1) + bbit;
                uint32_t off = (uint32_t)((kf >> 1) * 4096 + row * 64 + ((ch ^ (row & 3)) << 4));
                uint32_t kh4[4];
                ldm_x4(kh4[0], kh4[1], kh4[2], kh4[3], base + off);
#pragma unroll
                for (int mb = 0; mb < 2; mb++) {
                    mma_f16(sacc[mb][2 * np], fQ[mb][kf], kh4 + 0);
                    mma_f16(sacc[mb][2 * np + 1], fQ[mb][kf], kh4 + 2);
                }
            }
        }

#pragma unroll
        for (int mb = 0; mb < 2; mb++) {
            float rmax0 = -1e30f, rmax1 = -1e30f;
#pragma unroll
            for (int i = 0; i < 8; i++) {
                rmax0 = fmaxf(rmax0, fmaxf(sacc[mb][i][0], sacc[mb][i][1]));
                rmax1 = fmaxf(rmax1, fmaxf(sacc[mb][i][2], sacc[mb][i][3]));
            }
            rmax0 = fmaxf(rmax0, __shfl_xor_sync(0xffffffffu, rmax0, 1));
            rmax0 = fmaxf(rmax0, __shfl_xor_sync(0xffffffffu, rmax0, 2));
            rmax1 = fmaxf(rmax1, __shfl_xor_sync(0xffffffffu, rmax1, 1));
            rmax1 = fmaxf(rmax1, __shfl_xor_sync(0xffffffffu, rmax1, 2));
            float mn0 = fmaxf(mrun[mb][0], C2 * rmax0);
            float mn1 = fmaxf(mrun[mb][1], C2 * rmax1);
            float al0 = ex2(mrun[mb][0] - mn0);
            float al1 = ex2(mrun[mb][1] - mn1);
            mrun[mb][0] = mn0; mrun[mb][1] = mn1;
#pragma unroll
            for (int i = 0; i < 8; i++) {
                ctxa[mb][i][0] *= al0; ctxa[mb][i][1] *= al0;
                ctxa[mb][i][2] *= al1; ctxa[mb][i][3] *= al1;
            }
            float rs0 = 0.0f, rs1 = 0.0f;
#pragma unroll
            for (int i = 0; i < 8; i++) {
                sacc[mb][i][0] = ex2(fmaf(C2, sacc[mb][i][0], -mn0));
                sacc[mb][i][1] = ex2(fmaf(C2, sacc[mb][i][1], -mn0));
                sacc[mb][i][2] = ex2(fmaf(C2, sacc[mb][i][2], -mn1));
                sacc[mb][i][3] = ex2(fmaf(C2, sacc[mb][i][3], -mn1));
                rs0 += sacc[mb][i][0] + sacc[mb][i][1];
                rs1 += sacc[mb][i][2] + sacc[mb][i][3];
            }
            rs0 += __shfl_xor_sync(0xffffffffu, rs0, 1);
            rs0 += __shfl_xor_sync(0xffffffffu, rs0, 2);
            rs1 += __shfl_xor_sync(0xffffffffu, rs1, 1);
            rs1 += __shfl_xor_sync(0xffffffffu, rs1, 2);
            lrun[mb][0] = lrun[mb][0] * al0 + rs0;
            lrun[mb][1] = lrun[mb][1] * al1 + rs1;
        }

#pragma unroll
        for (int kf = 0; kf < 4; kf++) {
            uint32_t pH[2][4];
#pragma unroll
            for (int mb = 0; mb < 2; mb++) {
                pH[mb][0] = pack2h(sacc[mb][2 * kf][0], sacc[mb][2 * kf][1]);
                pH[mb][1] = pack2h(sacc[mb][2 * kf][2], sacc[mb][2 * kf][3]);
                pH[mb][2] = pack2h(sacc[mb][2 * kf + 1][0], sacc[mb][2 * kf + 1][1]);
                pH[mb][3] = pack2h(sacc[mb][2 * kf + 1][2], sacc[mb][2 * kf + 1][3]);
            }
#pragma unroll
            for (int np = 0; np < 4; np++) {
                int row = np * 16 + brow;
                int ch = ((kf & 1) << 1) + bbit;
                uint32_t off = (uint32_t)((kf >> 1) * 4096 + row * 64 + ((ch ^ (row & 3)) << 4));
                uint32_t vh4[4];
                ldm_x4(vh4[0], vh4[1], vh4[2], vh4[3], base + 8192 + off);
#pragma unroll
                for (int mb = 0; mb < 2; mb++) {
                    mma_f16(ctxa[mb][2 * np], pH[mb], vh4 + 0);
                    mma_f16(ctxa[mb][2 * np + 1], pH[mb], vh4 + 2);
                }
            }
        }
        __syncthreads();
    }

    const int b = bh >> 4, h = bh & 15;
    const int nl = (lane & 3) << 1;
#pragma unroll
    for (int mb = 0; mb < 2; mb++) {
        const float inv0 = 1.0f / lrun[mb][0];
        const float inv1 = 1.0f / lrun[mb][1];
        const int r0 = q0 + wid * 32 + mb * 16 + (lane >> 2);
#pragma unroll
        for (int nt = 0; nt < 8; nt++) {
            int d = nt * 8 + nl;
            size_t i0 = (size_t)(b * SEQ + r0) * DMODEL + h * 64 + d;
            *(uint32_t*)&s_c16[i0] = pack2h(ctxa[mb][nt][0] * inv0, ctxa[mb][nt][1] * inv0);
            size_t i1 = (size_t)(b * SEQ + r0 + 8) * DMODEL + h * 64 + d;
            *(uint32_t*)&s_c16[i1] = pack2h(ctxa[mb][nt][2] * inv1, ctxa[mb][nt][3] * inv1);
        }
    }
}

// ---------------------------------------------------------------------------
extern "C" void kernel_launch(void* const* d_in, const int* in_sizes, int n_in,
                              void* d_out, int out_size)
{
    (void)in_sizes; (void)n_in; (void)out_size;
    const float* q  = (const float*)d_in[0];
    const float* k  = (const float*)d_in[1];
    const float* v  = (const float*)d_in[2];
    const float* Wq = (const float*)d_in[3];
    const float* bq = (const float*)d_in[4];
    const float* Wk = (const float*)d_in[5];
    const float* bk = (const float*)d_in[6];
    const float* Wv = (const float*)d_in[7];
    const float* bv = (const float*)d_in[8];
    const float* Wo = (const float*)d_in[9];
    const float* bo = (const float*)d_in[10];
    float* out = (float*)d_out;

    __half *xq, *xk, *xv, *c16, *w, *aq, *ak, *avt;
    cudaGetSymbolAddress((void**)&xq, s_xq);
    cudaGetSymbolAddress((void**)&xk, s_xk);
    cudaGetSymbolAddress((void**)&xv, s_xv);
    cudaGetSymbolAddress((void**)&c16, s_c16);
    cudaGetSymbolAddress((void**)&w, s_w);
    cudaGetSymbolAddress((void**)&aq, a_q);
    cudaGetSymbolAddress((void**)&ak, a_k);
    cudaGetSymbolAddress((void**)&avt, a_vt);

    const int GSM = 3 * GSTG;   // 72KB
    cudaFuncSetAttribute((const void*)gemm_mma<0>, cudaFuncAttributeMaxDynamicSharedMemorySize, GSM);
    cudaFuncSetAttribute((const void*)gemm_mma<2>, cudaFuncAttributeMaxDynamicSharedMemorySize, GSM);
    cudaFuncSetAttribute((const void*)gemm_mma<3>, cudaFuncAttributeMaxDynamicSharedMemorySize, GSM);
    cudaFuncSetAttribute(attn_mma, cudaFuncAttributeMaxDynamicSharedMemorySize, 49152);

    const size_t WSZ = (size_t)DMODEL * DMODEL;
    const int NX4 = MROWS * DMODEL / 4;    // 1048576
    const int NW4 = DMODEL * DMODEL / 4;   // 262144

    {
        CvtArgs ci;
        ci.x[0] = q; ci.y[0] = xq;
        ci.x[1] = k; ci.y[1] = xk;
        ci.x[2] = v; ci.y[2] = xv;
        ci.x[3] = q; ci.y[3] = xq;    // unused
        cvt_multi<<<dim3(NX4 / 256, 1, 3), 256>>>(ci, NX4);
        CvtArgs cw;
        cw.x[0] = Wq; cw.y[0] = w + 0 * WSZ;
        cw.x[1] = Wk; cw.y[1] = w + 1 * WSZ;
        cw.x[2] = Wv; cw.y[2] = w + 2 * WSZ;
        cw.x[3] = Wo; cw.y[3] = w + 3 * WSZ;
        cvt_multi<<<dim3(NW4 / 256, 1, 4), 256>>>(cw, NW4);
    }

    dim3 gg(DMODEL / 128, MROWS / 256);  // (8, 16)
    gemm_mma<3><<<gg, 512, GSM>>>(xq, w + 0 * WSZ, bq, nullptr, aq);
    gemm_mma<3><<<gg, 512, GSM>>>(xk, w + 1 * WSZ, bk, nullptr, ak);
    gemm_mma<2><<<gg, 512, GSM>>>(xv, w + 2 * WSZ, bv, nullptr, avt);

    attn_mma<<<dim3(BHN, SEQ / 128), 128, 49152>>>();

    gemm_mma<0><<<gg, 512, GSM>>>(c16, w + 3 * WSZ, bo, out, nullptr);
}

// round 17
// speedup vs baseline: 1.1784x; 1.1784x over previous
#include <cuda_runtime.h>
#include <cuda_fp16.h>
#include <cstdint>
#include <math.h>

#define H 16
#define DMODEL 1024
#define DK 64
#define NB 2
#define SEQ 2048
#define MROWS (NB*SEQ)   // 4096
#define BHN (NB*H)       // 32

// ---------------- scratch (device globals; no allocation allowed) ----------
__device__ __half s_xq[MROWS * DMODEL];
__device__ __half s_xk[MROWS * DMODEL];
__device__ __half s_xv[MROWS * DMODEL];
__device__ __half s_c16[MROWS * DMODEL];
__device__ __half s_w[4][DMODEL * DMODEL];
__device__ __half a_q[BHN * SEQ * DK];
__device__ __half a_k[BHN * SEQ * DK];
__device__ __half a_vt[BHN * DK * SEQ];

// ---------------- helpers ---------------------------------------------------
static __device__ __forceinline__ uint32_t smem_u32(const void* p) {
    uint32_t a;
    asm("{ .reg .u64 t; cvta.to.shared.u64 t, %1; cvt.u32.u64 %0, t; }"
        : "=r"(a) : "l"(p));
    return a;
}
static __device__ __forceinline__ void cp16(uint32_t s, const void* g) {
    asm volatile("cp.async.cg.shared.global [%0], [%1], 16;" :: "r"(s), "l"(g));
}
#define CP_COMMIT() asm volatile("cp.async.commit_group;")
template <int N>
static __device__ __forceinline__ void cp_wait() {
    asm volatile("cp.async.wait_group %0;" :: "n"(N));
}
static __device__ __forceinline__ void ldm_x4(uint32_t& r0, uint32_t& r1,
                                              uint32_t& r2, uint32_t& r3, uint32_t a) {
    asm volatile("ldmatrix.sync.aligned.m8n8.x4.shared.b16 {%0,%1,%2,%3}, [%4];"
                 : "=r"(r0), "=r"(r1), "=r"(r2), "=r"(r3) : "r"(a));
}
static __device__ __forceinline__ void mma_f16(float* c, const uint32_t* a,
                                               const uint32_t* b) {
    asm volatile(
        "mma.sync.aligned.m16n8k16.row.col.f32.f16.f16.f32 "
        "{%0,%1,%2,%3}, {%4,%5,%6,%7}, {%8,%9}, {%0,%1,%2,%3};"
        : "+f"(c[0]), "+f"(c[1]), "+f"(c[2]), "+f"(c[3])
        : "r"(a[0]), "r"(a[1]), "r"(a[2]), "r"(a[3]), "r"(b[0]), "r"(b[1]));
}
static __device__ __forceinline__ float ex2(float x) {
    float y; asm("ex2.approx.f32 %0, %1;" : "=f"(y) : "f"(x)); return y;
}
static __device__ __forceinline__ uint32_t pack2h(float a, float b) {
    __half2 h2 = __halves2half2(__float2half_rn(a), __float2half_rn(b));
    return *(uint32_t*)&h2;
}

// ---------------------------------------------------------------------------
// batched convert fp32 -> fp16 ; blockIdx.z selects job
// ---------------------------------------------------------------------------
struct CvtArgs {
    const float* x[4];
    __half* y[4];
};

__global__ void cvt_multi(CvtArgs ja, int n4)
{
    const float* x = ja.x[blockIdx.z];
    uint32_t* y = (uint32_t*)ja.y[blockIdx.z];
    int i = blockIdx.x * 256 + threadIdx.x;
    if (i >= n4) return;
    float4 v = ((const float4*)x)[i];
    y[2 * i] = pack2h(v.x, v.y);
    y[2 * i + 1] = pack2h(v.z, v.w);
}

// ---------------------------------------------------------------------------
// fp16 single-pass GEMM: 256x128 CTA tile, 8 warps (4m x 2n), warp 64x64.
// BK=64 (128B smem rows, c^(row&7) swizzle): 16 iterations, half the
// barriers of R15; 256 MMAs/warp of independent work between syncs.
// Stage 48KB (A 32K | B 16K), 3 stages = 144KB, cp.async pipeline.
// k16 accumulation order identical to R15 -> bitwise-same results.
// Epilogue modes: 0 fp32 flat | 2 transposed fp16 | 3 head fp16.
// ---------------------------------------------------------------------------
#define NIT3 16      // 1024 / 64
#define GSTG 49152   // 48KB per stage

template <int MODE>
__global__ void __launch_bounds__(256, 1)
gemm_mma(const __half* __restrict__ A, const __half* __restrict__ B,
         const float* __restrict__ bias, float* __restrict__ Y,
         __half* __restrict__ Yh)
{
    extern __shared__ __align__(128) char dsm[];
    const uint32_t sS = smem_u32(dsm);     // 3 stages x 48KB

    const int tid = threadIdx.x;
    const int wid = tid >> 5, lane = tid & 31;
    const int wm = wid >> 1, wn = wid & 1;      // 4m x 2n
    const int m0 = blockIdx.y << 8, n0 = blockIdx.x << 7;

    float acc[4][8][4];
#pragma unroll
    for (int i = 0; i < 4; i++)
#pragma unroll
        for (int j = 0; j < 8; j++)
#pragma unroll
            for (int u = 0; u < 4; u++) acc[i][j][u] = 0.0f;

    const int lc = tid & 7;                 // 16B chunk within 128B row

    auto load_it = [&](int it3, int st) {
        const int kk = it3 << 6;            // k offset (fp16 elems)
        uint32_t b = sS + (uint32_t)st * GSTG;
        // A: 256 rows x 8 chunks = 2048, 8 per thread
#pragma unroll
        for (int j = 0; j < 8; j++) {
            int cid = tid + 256 * j;
            int row = cid >> 3;
            uint32_t off = (uint32_t)(row * 128 + ((lc ^ (row & 7)) << 4));
            size_t ga = (size_t)(m0 + row) * DMODEL + kk + lc * 8;
            cp16(b + off, A + ga);
        }
        // B: 128 rows x 8 chunks = 1024, 4 per thread
#pragma unroll
        for (int j = 0; j < 4; j++) {
            int cid = tid + 256 * j;
            int row = cid >> 3;
            uint32_t off = (uint32_t)(row * 128 + ((lc ^ (row & 7)) << 4));
            size_t gb = (size_t)(n0 + row) * DMODEL + kk + lc * 8;
            cp16(b + 32768u + off, B + gb);
        }
        CP_COMMIT();
    };

    const int arow = wm * 64 + (lane & 15);
    const int abit = lane >> 4;
    const int brow = wn * 64 + (lane & 7) + ((lane >> 4) & 1) * 8;
    const int bbit = (lane >> 3) & 1;

    load_it(0, 0);
    load_it(1, 1);

    int st = 0;
    for (int it = 0; it < NIT3; ++it) {
        if (it + 1 < NIT3) cp_wait<1>(); else cp_wait<0>();
        __syncthreads();
        if (it + 2 < NIT3) {
            int st2 = st + 2; if (st2 >= 3) st2 -= 3;
            load_it(it + 2, st2);
        }
        const uint32_t sb = sS + (uint32_t)st * GSTG;
#pragma unroll
        for (int ks = 0; ks < 4; ks++) {
            uint32_t bh4[4][4];
#pragma unroll
            for (int np = 0; np < 4; np++) {
                int row = brow + np * 16;
                int ch = 2 * ks + bbit;
                uint32_t off = (uint32_t)(row * 128 + ((ch ^ (row & 7)) << 4));
                ldm_x4(bh4[np][0], bh4[np][1], bh4[np][2], bh4[np][3], sb + 32768u + off);
            }
            uint32_t af[4][4];
#pragma unroll
            for (int mt = 0; mt < 4; mt++) {
                int row = arow + mt * 16;
                int ch = 2 * ks + abit;
                uint32_t ad = sb + (uint32_t)(row * 128 + ((ch ^ (row & 7)) << 4));
                ldm_x4(af[mt][0], af[mt][1], af[mt][2], af[mt][3], ad);
            }
#pragma unroll
            for (int mt = 0; mt < 4; mt++)
#pragma unroll
                for (int nn = 0; nn < 8; nn++)
                    mma_f16(acc[mt][nn], af[mt], bh4[nn >> 1] + (nn & 1) * 2);
        }
        if (++st == 3) st = 0;
    }

    const int ml = lane >> 2;
    const int nl = (lane & 3) << 1;
#pragma unroll
    for (int mt = 0; mt < 4; mt++) {
#pragma unroll
        for (int half = 0; half < 2; half++) {
            int m = m0 + wm * 64 + mt * 16 + ml + half * 8;
#pragma unroll
            for (int nn = 0; nn < 8; nn++) {
                int n = n0 + wn * 64 + nn * 8 + nl;
                float x = acc[mt][nn][2 * half + 0] + bias[n + 0];
                float y = acc[mt][nn][2 * half + 1] + bias[n + 1];
                if (MODE == 0) {
                    float2 o; o.x = x; o.y = y;
                    *(float2*)&Y[(size_t)m * DMODEL + n] = o;
                } else {
                    int bb = m >> 11, s = m & 2047;
                    int h = n >> 6, d = n & 63;
                    if (MODE == 3) {
                        size_t idx = (size_t)((bb * H + h) * SEQ + s) * DK + d;
                        *(uint32_t*)&Yh[idx] = pack2h(x, y);
                    } else {
                        size_t base = (size_t)((bb * H + h) * DK + d) * SEQ + s;
                        Yh[base] = __float2half_rn(x);
                        Yh[base + SEQ] = __float2half_rn(y);
                    }
                }
            }
        }
    }
}

// ---------------------------------------------------------------------------
// fp16 flash attention (R15-proven, frozen): 4 warps x 32 q-rows, 128 thr,
// 2 CTA/SM.  BQ=128, BKV=64.  Q frags resident; K/V^T double-buffered.
// Smem: Q 16K | 2 x (K 8K | V 8K) = 48KB.
// ---------------------------------------------------------------------------
__global__ void __launch_bounds__(128, 2)
attn_mma()
{
    extern __shared__ __align__(128) char dsm[];
    const uint32_t sbase = smem_u32(dsm);
    const uint32_t sQ = sbase;
    const uint32_t sKV = sbase + 16384;

    const int bh = blockIdx.x;
    const int q0 = blockIdx.y << 7;
    const int tid = threadIdx.x, wid = tid >> 5, lane = tid & 31;

    const __half* qg = a_q + (size_t)bh * SEQ * DK;
    const __half* kg = a_k + (size_t)bh * SEQ * DK;
    const __half* vg = a_vt + (size_t)bh * DK * SEQ;

#pragma unroll
    for (int j = 0; j < 8; j++) {
        int cid = tid + 128 * j;
        int hr = cid >> 2, c = cid & 3;
        int qrow = hr & 127, panel = hr >> 7;
        uint32_t off = (uint32_t)(hr * 64 + ((c ^ (hr & 3)) << 4));
        const size_t src = (size_t)(q0 + qrow) * DK + panel * 32 + c * 8;
        cp16(sQ + off, qg + src);
    }
    CP_COMMIT();
    cp_wait<0>();
    __syncthreads();

    uint32_t fQ[2][4][4];
#pragma unroll
    for (int mb = 0; mb < 2; mb++) {
        const int row = wid * 32 + mb * 16 + (lane & 15);
#pragma unroll
        for (int kf = 0; kf < 4; kf++) {
            int ch = ((kf & 1) << 1) + (lane >> 4);
            uint32_t off = (uint32_t)((kf >> 1) * 8192 + row * 64 + ((ch ^ (row & 3)) << 4));
            ldm_x4(fQ[mb][kf][0], fQ[mb][kf][1], fQ[mb][kf][2], fQ[mb][kf][3], sQ + off);
        }
    }

    float ctxa[2][8][4];
#pragma unroll
    for (int mb = 0; mb < 2; mb++)
#pragma unroll
        for (int i = 0; i < 8; i++)
#pragma unroll
            for (int u = 0; u < 4; u++) ctxa[mb][i][u] = 0.0f;
    float mrun[2][2], lrun[2][2];
#pragma unroll
    for (int mb = 0; mb < 2; mb++) {
        mrun[mb][0] = -1e30f; mrun[mb][1] = -1e30f;
        lrun[mb][0] = 0.0f;   lrun[mb][1] = 0.0f;
    }

    auto load_kv = [&](int kt, int buf) {
        uint32_t base = sKV + buf * 16384;
#pragma unroll
        for (int j = 0; j < 4; j++) {
            int cid = tid + 128 * j;
            int hr = cid >> 2, c = cid & 3;
            uint32_t off = (uint32_t)(hr * 64 + ((c ^ (hr & 3)) << 4));
            int lo6 = hr & 63, pan = hr >> 6;
            size_t ksrc = (size_t)(kt + lo6) * DK + pan * 32 + c * 8;
            size_t vsrc = (size_t)lo6 * SEQ + kt + pan * 32 + c * 8;
            cp16(base + off, kg + ksrc);
            cp16(base + 8192 + off, vg + vsrc);
        }
        CP_COMMIT();
    };

    const int brow = (lane & 7) + ((lane >> 4) & 1) * 8;
    const int bbit = (lane >> 3) & 1;
    const float C2 = 0.18033688f;   // log2(e)/8

    load_kv(0, 0);

    for (int t = 0; t < SEQ / 64; ++t) {
        if (t + 1 < SEQ / 64) { load_kv((t + 1) * 64, (t + 1) & 1); cp_wait<1>(); }
        else cp_wait<0>();
        __syncthreads();

        const uint32_t base = sKV + (t & 1) * 16384;

        float sacc[2][8][4];
#pragma unroll
        for (int mb = 0; mb < 2; mb++)
#pragma unroll
            for (int i = 0; i < 8; i++)
#pragma unroll
                for (int u = 0; u < 4; u++) sacc[mb][i][u] = 0.0f;

#pragma unroll
        for (int kf = 0; kf < 4; kf++) {
#pragma unroll
            for (int np = 0; np < 4; np++) {
                int row = np * 16 + brow;
                int ch = ((kf & 1) << 1) + bbit;
                uint32_t off = (uint32_t)((kf >> 1) * 4096 + row * 64 + ((ch ^ (row & 3)) << 4));
                uint32_t kh4[4];
                ldm_x4(kh4[0], kh4[1], kh4[2], kh4[3], base + off);
#pragma unroll
                for (int mb = 0; mb < 2; mb++) {
                    mma_f16(sacc[mb][2 * np], fQ[mb][kf], kh4 + 0);
                    mma_f16(sacc[mb][2 * np + 1], fQ[mb][kf], kh4 + 2);
                }
            }
        }

#pragma unroll
        for (int mb = 0; mb < 2; mb++) {
            float rmax0 = -1e30f, rmax1 = -1e30f;
#pragma unroll
            for (int i = 0; i < 8; i++) {
                rmax0 = fmaxf(rmax0, fmaxf(sacc[mb][i][0], sacc[mb][i][1]));
                rmax1 = fmaxf(rmax1, fmaxf(sacc[mb][i][2], sacc[mb][i][3]));
            }
            rmax0 = fmaxf(rmax0, __shfl_xor_sync(0xffffffffu, rmax0, 1));
            rmax0 = fmaxf(rmax0, __shfl_xor_sync(0xffffffffu, rmax0, 2));
            rmax1 = fmaxf(rmax1, __shfl_xor_sync(0xffffffffu, rmax1, 1));
            rmax1 = fmaxf(rmax1, __shfl_xor_sync(0xffffffffu, rmax1, 2));
            float mn0 = fmaxf(mrun[mb][0], C2 * rmax0);
            float mn1 = fmaxf(mrun[mb][1], C2 * rmax1);
            float al0 = ex2(mrun[mb][0] - mn0);
            float al1 = ex2(mrun[mb][1] - mn1);
            mrun[mb][0] = mn0; mrun[mb][1] = mn1;
#pragma unroll
            for (int i = 0; i < 8; i++) {
                ctxa[mb][i][0] *= al0; ctxa[mb][i][1] *= al0;
                ctxa[mb][i][2] *= al1; ctxa[mb][i][3] *= al1;
            }
            float rs0 = 0.0f, rs1 = 0.0f;
#pragma unroll
            for (int i = 0; i < 8; i++) {
                sacc[mb][i][0] = ex2(fmaf(C2, sacc[mb][i][0], -mn0));
                sacc[mb][i][1] = ex2(fmaf(C2, sacc[mb][i][1], -mn0));
                sacc[mb][i][2] = ex2(fmaf(C2, sacc[mb][i][2], -mn1));
                sacc[mb][i][3] = ex2(fmaf(C2, sacc[mb][i][3], -mn1));
                rs0 += sacc[mb][i][0] + sacc[mb][i][1];
                rs1 += sacc[mb][i][2] + sacc[mb][i][3];
            }
            rs0 += __shfl_xor_sync(0xffffffffu, rs0, 1);
            rs0 += __shfl_xor_sync(0xffffffffu, rs0, 2);
            rs1 += __shfl_xor_sync(0xffffffffu, rs1, 1);
            rs1 += __shfl_xor_sync(0xffffffffu, rs1, 2);
            lrun[mb][0] = lrun[mb][0] * al0 + rs0;
            lrun[mb][1] = lrun[mb][1] * al1 + rs1;
        }

#pragma unroll
        for (int kf = 0; kf < 4; kf++) {
            uint32_t pH[2][4];
#pragma unroll
            for (int mb = 0; mb < 2; mb++) {
                pH[mb][0] = pack2h(sacc[mb][2 * kf][0], sacc[mb][2 * kf][1]);
                pH[mb][1] = pack2h(sacc[mb][2 * kf][2], sacc[mb][2 * kf][3]);
                pH[mb][2] = pack2h(sacc[mb][2 * kf + 1][0], sacc[mb][2 * kf + 1][1]);
                pH[mb][3] = pack2h(sacc[mb][2 * kf + 1][2], sacc[mb][2 * kf + 1][3]);
            }
#pragma unroll
            for (int np = 0; np < 4; np++) {
                int row = np * 16 + brow;
                int ch = ((kf & 1) << 1) + bbit;
                uint32_t off = (uint32_t)((kf >> 1) * 4096 + row * 64 + ((ch ^ (row & 3)) << 4));
                uint32_t vh4[4];
                ldm_x4(vh4[0], vh4[1], vh4[2], vh4[3], base + 8192 + off);
#pragma unroll
                for (int mb = 0; mb < 2; mb++) {
                    mma_f16(ctxa[mb][2 * np], pH[mb], vh4 + 0);
                    mma_f16(ctxa[mb][2 * np + 1], pH[mb], vh4 + 2);
                }
            }
        }
        __syncthreads();
    }

    const int b = bh >> 4, h = bh & 15;
    const int nl = (lane & 3) << 1;
#pragma unroll
    for (int mb = 0; mb < 2; mb++) {
        const float inv0 = 1.0f / lrun[mb][0];
        const float inv1 = 1.0f / lrun[mb][1];
        const int r0 = q0 + wid * 32 + mb * 16 + (lane >> 2);
#pragma unroll
        for (int nt = 0; nt < 8; nt++) {
            int d = nt * 8 + nl;
            size_t i0 = (size_t)(b * SEQ + r0) * DMODEL + h * 64 + d;
            *(uint32_t*)&s_c16[i0] = pack2h(ctxa[mb][nt][0] * inv0, ctxa[mb][nt][1] * inv0);
            size_t i1 = (size_t)(b * SEQ + r0 + 8) * DMODEL + h * 64 + d;
            *(uint32_t*)&s_c16[i1] = pack2h(ctxa[mb][nt][2] * inv1, ctxa[mb][nt][3] * inv1);
        }
    }
}

// ---------------------------------------------------------------------------
extern "C" void kernel_launch(void* const* d_in, const int* in_sizes, int n_in,
                              void* d_out, int out_size)
{
    (void)in_sizes; (void)n_in; (void)out_size;
    const float* q  = (const float*)d_in[0];
    const float* k  = (const float*)d_in[1];
    const float* v  = (const float*)d_in[2];
    const float* Wq = (const float*)d_in[3];
    const float* bq = (const float*)d_in[4];
    const float* Wk = (const float*)d_in[5];
    const float* bk = (const float*)d_in[6];
    const float* Wv = (const float*)d_in[7];
    const float* bv = (const float*)d_in[8];
    const float* Wo = (const float*)d_in[9];
    const float* bo = (const float*)d_in[10];
    float* out = (float*)d_out;

    __half *xq, *xk, *xv, *c16, *w, *aq, *ak, *avt;
    cudaGetSymbolAddress((void**)&xq, s_xq);
    cudaGetSymbolAddress((void**)&xk, s_xk);
    cudaGetSymbolAddress((void**)&xv, s_xv);
    cudaGetSymbolAddress((void**)&c16, s_c16);
    cudaGetSymbolAddress((void**)&w, s_w);
    cudaGetSymbolAddress((void**)&aq, a_q);
    cudaGetSymbolAddress((void**)&ak, a_k);
    cudaGetSymbolAddress((void**)&avt, a_vt);

    const int GSM = 3 * GSTG;   // 144KB
    cudaFuncSetAttribute((const void*)gemm_mma<0>, cudaFuncAttributeMaxDynamicSharedMemorySize, GSM);
    cudaFuncSetAttribute((const void*)gemm_mma<2>, cudaFuncAttributeMaxDynamicSharedMemorySize, GSM);
    cudaFuncSetAttribute((const void*)gemm_mma<3>, cudaFuncAttributeMaxDynamicSharedMemorySize, GSM);
    cudaFuncSetAttribute(attn_mma, cudaFuncAttributeMaxDynamicSharedMemorySize, 49152);

    const size_t WSZ = (size_t)DMODEL * DMODEL;
    const int NX4 = MROWS * DMODEL / 4;    // 1048576
    const int NW4 = DMODEL * DMODEL / 4;   // 262144

    {
        CvtArgs ci;
        ci.x[0] = q; ci.y[0] = xq;
        ci.x[1] = k; ci.y[1] = xk;
        ci.x[2] = v; ci.y[2] = xv;
        ci.x[3] = q; ci.y[3] = xq;    // unused
        cvt_multi<<<dim3(NX4 / 256, 1, 3), 256>>>(ci, NX4);
        CvtArgs cw;
        cw.x[0] = Wq; cw.y[0] = w + 0 * WSZ;
        cw.x[1] = Wk; cw.y[1] = w + 1 * WSZ;
        cw.x[2] = Wv; cw.y[2] = w + 2 * WSZ;
        cw.x[3] = Wo; cw.y[3] = w + 3 * WSZ;
        cvt_multi<<<dim3(NW4 / 256, 1, 4), 256>>>(cw, NW4);
    }

    dim3 gg(DMODEL / 128, MROWS / 256);  // (8, 16)
    gemm_mma<3><<<gg, 256, GSM>>>(xq, w + 0 * WSZ, bq, nullptr, aq);
    gemm_mma<3><<<gg, 256, GSM>>>(xk, w + 1 * WSZ, bk, nullptr, ak);
    gemm_mma<2><<<gg, 256, GSM>>>(xv, w + 2 * WSZ, bv, nullptr, avt);

    attn_mma<<<dim3(BHN, SEQ / 128), 128, 49152>>>();

    gemm_mma<0><<<gg, 256, GSM>>>(c16, w + 3 * WSZ, bo, out, nullptr);
}